// round 1
// baseline (speedup 1.0000x reference)
#include <cuda_runtime.h>

// GRU_67714454389230: 2-layer GRU (H=12, IN=18) + fc(12->1), B=4096, T=512.
// Strategy: SIMT recurrent scan. 4 lanes per batch element; lane `sub` owns
// hidden units {3*sub .. 3*sub+2} and computes the 9 (gate,unit) dots per layer.
// Hidden vectors are exchanged via width-4 warp shuffles each step.
// Weights in shared memory (float4 rows, conflict-free), biases in registers.

static constexpr int IN_DIM = 18;
static constexpr int HID    = 12;
static constexpr int G3     = 36;     // 3*HID
static constexpr int BATCH  = 4096;
static constexpr int SEQ    = 512;
static constexpr int THREADS = 128;   // 32 batch elements per block
static constexpr int GRID    = (BATCH * 4) / THREADS;  // 128 blocks

__device__ __forceinline__ float fast_sig(float x) {
    // 1/(1+e^-x); __expf saturates correctly at both ends.
    return 1.0f / (1.0f + __expf(-x));
}
__device__ __forceinline__ float fast_tanh(float x) {
    // tanh(x) = 1 - 2/(e^{2x}+1); correct limits at +/-inf.
    return 1.0f - 2.0f / (__expf(2.0f * x) + 1.0f);
}

__global__ __launch_bounds__(THREADS, 1)
void gru_scan_kernel(const float* __restrict__ x,
                     const float* __restrict__ w_ih0, const float* __restrict__ w_hh0,
                     const float* __restrict__ b_ih0, const float* __restrict__ b_hh0,
                     const float* __restrict__ w_ih1, const float* __restrict__ w_hh1,
                     const float* __restrict__ b_ih1, const float* __restrict__ b_hh1,
                     const float* __restrict__ fc_w, const float* __restrict__ fc_b,
                     float* __restrict__ out)
{
    // Shared weights. w_ih0 rows padded 18 -> 20 floats (zero pad) so every row
    // is 5 aligned float4 chunks. Bases are 16B aligned; row strides (20,12
    // floats) keep float4 alignment for every row.
    __shared__ __align__(16) float s_ih0[G3 * 20];
    __shared__ __align__(16) float s_hh0[G3 * 12];
    __shared__ __align__(16) float s_ih1[G3 * 12];
    __shared__ __align__(16) float s_hh1[G3 * 12];

    const int tid = threadIdx.x;
    for (int i = tid; i < G3 * 20; i += THREADS) {
        int r = i / 20, c = i % 20;
        s_ih0[i] = (c < IN_DIM) ? w_ih0[r * IN_DIM + c] : 0.0f;
    }
    for (int i = tid; i < G3 * 12; i += THREADS) s_hh0[i] = w_hh0[i];
    for (int i = tid; i < G3 * 12; i += THREADS) s_ih1[i] = w_ih1[i];
    for (int i = tid; i < G3 * 12; i += THREADS) s_hh1[i] = w_hh1[i];
    __syncthreads();

    const int g     = blockIdx.x * THREADS + tid;
    const int batch = g >> 2;          // 4 lanes per batch element
    const int sub   = g & 3;           // which quad lane
    const int u0    = sub * 3;         // first owned hidden unit

    // Bias registers; idx = gate*3 + j  (gate: 0=r,1=z,2=n), row = gate*12+u0+j
    float bi0[9], bh0[9], bi1[9], bh1[9];
#pragma unroll
    for (int gate = 0; gate < 3; ++gate)
#pragma unroll
        for (int j = 0; j < 3; ++j) {
            int row = gate * HID + u0 + j;
            int k = gate * 3 + j;
            bi0[k] = b_ih0[row]; bh0[k] = b_hh0[row];
            bi1[k] = b_ih1[row]; bh1[k] = b_hh1[row];
        }
    float fcw[HID];
#pragma unroll
    for (int u = 0; u < HID; ++u) fcw[u] = fc_w[u];
    const float fcb = fc_b[0];

    float h1v[HID], h2v[HID];
#pragma unroll
    for (int u = 0; u < HID; ++u) { h1v[u] = 0.0f; h2v[u] = 0.0f; }

    // x row for this batch: 18 floats = 9 float2 (always 8B aligned: 18 even).
    const float2* xp = (const float2*)(x + (size_t)batch * SEQ * IN_DIM);
    float* op = out + (size_t)batch * SEQ;

    // Software-pipelined x: xn holds row for step t; prefetch t+1 during compute.
    float2 xn[9];
#pragma unroll
    for (int i = 0; i < 9; ++i) xn[i] = xp[i];

    for (int t = 0; t < SEQ; ++t) {
        float xv[20];
#pragma unroll
        for (int i = 0; i < 9; ++i) { xv[2 * i] = xn[i].x; xv[2 * i + 1] = xn[i].y; }
        xv[18] = 0.0f; xv[19] = 0.0f;

        // Prefetch next step's x (predicated on the final iteration).
        const float2* xnext = xp + (size_t)(t + 1) * 9;
#pragma unroll
        for (int i = 0; i < 9; ++i)
            xn[i] = (t + 1 < SEQ) ? xnext[i] : make_float2(0.0f, 0.0f);

        // ================= layer 1 =================
        float gi[9], gh[9];
#pragma unroll
        for (int k = 0; k < 9; ++k) { gi[k] = bi0[k]; gh[k] = bh0[k]; }

        // input projection: 5 float4 chunks over padded k=0..19
#pragma unroll
        for (int c = 0; c < 5; ++c) {
            const float x0 = xv[4 * c + 0], x1 = xv[4 * c + 1];
            const float x2 = xv[4 * c + 2], x3 = xv[4 * c + 3];
#pragma unroll
            for (int gate = 0; gate < 3; ++gate)
#pragma unroll
                for (int j = 0; j < 3; ++j) {
                    const float4 w = *(const float4*)&s_ih0[(gate * HID + u0 + j) * 20 + 4 * c];
                    float a = gi[gate * 3 + j];
                    a = fmaf(x0, w.x, a); a = fmaf(x1, w.y, a);
                    a = fmaf(x2, w.z, a); a = fmaf(x3, w.w, a);
                    gi[gate * 3 + j] = a;
                }
        }
        // hidden projection: 3 float4 chunks over k=0..11
#pragma unroll
        for (int c = 0; c < 3; ++c) {
            const float h0 = h1v[4 * c + 0], h1 = h1v[4 * c + 1];
            const float h2 = h1v[4 * c + 2], h3 = h1v[4 * c + 3];
#pragma unroll
            for (int gate = 0; gate < 3; ++gate)
#pragma unroll
                for (int j = 0; j < 3; ++j) {
                    const float4 w = *(const float4*)&s_hh0[(gate * HID + u0 + j) * 12 + 4 * c];
                    float a = gh[gate * 3 + j];
                    a = fmaf(h0, w.x, a); a = fmaf(h1, w.y, a);
                    a = fmaf(h2, w.z, a); a = fmaf(h3, w.w, a);
                    gh[gate * 3 + j] = a;
                }
        }
        float hn1[3];
#pragma unroll
        for (int j = 0; j < 3; ++j) {
            float r = fast_sig(gi[j] + gh[j]);
            float z = fast_sig(gi[3 + j] + gh[3 + j]);
            float n = fast_tanh(fmaf(r, gh[6 + j], gi[6 + j]));
            float h = h1v[u0 + j];
            hn1[j] = fmaf(z, h - n, n);   // (1-z)*n + z*h
        }
        // broadcast new h1 across the quad (unit k owned by lane k/3, slot k%3)
#pragma unroll
        for (int k = 0; k < HID; ++k)
            h1v[k] = __shfl_sync(0xffffffffu, hn1[k % 3], k / 3, 4);

        // ================= layer 2 =================
#pragma unroll
        for (int k = 0; k < 9; ++k) { gi[k] = bi1[k]; gh[k] = bh1[k]; }
#pragma unroll
        for (int c = 0; c < 3; ++c) {
            const float a0 = h1v[4 * c + 0], a1 = h1v[4 * c + 1];
            const float a2 = h1v[4 * c + 2], a3 = h1v[4 * c + 3];
            const float p0 = h2v[4 * c + 0], p1 = h2v[4 * c + 1];
            const float p2 = h2v[4 * c + 2], p3 = h2v[4 * c + 3];
#pragma unroll
            for (int gate = 0; gate < 3; ++gate)
#pragma unroll
                for (int j = 0; j < 3; ++j) {
                    const int off = (gate * HID + u0 + j) * 12 + 4 * c;
                    const float4 wi = *(const float4*)&s_ih1[off];
                    const float4 wh = *(const float4*)&s_hh1[off];
                    float a = gi[gate * 3 + j];
                    a = fmaf(a0, wi.x, a); a = fmaf(a1, wi.y, a);
                    a = fmaf(a2, wi.z, a); a = fmaf(a3, wi.w, a);
                    gi[gate * 3 + j] = a;
                    float b = gh[gate * 3 + j];
                    b = fmaf(p0, wh.x, b); b = fmaf(p1, wh.y, b);
                    b = fmaf(p2, wh.z, b); b = fmaf(p3, wh.w, b);
                    gh[gate * 3 + j] = b;
                }
        }
        float hn2[3];
#pragma unroll
        for (int j = 0; j < 3; ++j) {
            float r = fast_sig(gi[j] + gh[j]);
            float z = fast_sig(gi[3 + j] + gh[3 + j]);
            float n = fast_tanh(fmaf(r, gh[6 + j], gi[6 + j]));
            float h = h2v[u0 + j];
            hn2[j] = fmaf(z, h - n, n);
        }
#pragma unroll
        for (int k = 0; k < HID; ++k)
            h2v[k] = __shfl_sync(0xffffffffu, hn2[k % 3], k / 3, 4);

        // ================= fc =================
        if (sub == 0) {
            float o = fcb;
#pragma unroll
            for (int u = 0; u < HID; ++u) o = fmaf(fcw[u], h2v[u], o);
            op[t] = o;
        }
    }
}

extern "C" void kernel_launch(void* const* d_in, const int* in_sizes, int n_in,
                              void* d_out, int out_size) {
    const float* x     = (const float*)d_in[0];
    const float* w_ih0 = (const float*)d_in[1];
    const float* w_hh0 = (const float*)d_in[2];
    const float* b_ih0 = (const float*)d_in[3];
    const float* b_hh0 = (const float*)d_in[4];
    const float* w_ih1 = (const float*)d_in[5];
    const float* w_hh1 = (const float*)d_in[6];
    const float* b_ih1 = (const float*)d_in[7];
    const float* b_hh1 = (const float*)d_in[8];
    const float* fc_w  = (const float*)d_in[9];
    const float* fc_b  = (const float*)d_in[10];
    float* out = (float*)d_out;

    gru_scan_kernel<<<GRID, THREADS>>>(x, w_ih0, w_hh0, b_ih0, b_hh0,
                                       w_ih1, w_hh1, b_ih1, b_hh1,
                                       fc_w, fc_b, out);
}